// round 14
// baseline (speedup 1.0000x reference)
#include <cuda_runtime.h>
#include <math.h>

#define BB 8
#define HH 96
#define WW 96
#define CC 180
#define NN (HH*WW)
#define WF 49
#define NF (HH*WF)
#define HIDV 360
#define H2V 720
#define PD 16
#define FFT_RES_C 0.15f
#define CONV_SCALE_C 0.01f
#define EPS_C 1e-5f

__device__ __align__(16) float g_ximg[BB*CC*NN];
__device__ float g_cmean[BB*CC];
__device__ float g_gates[BB*3];
__device__ float g_bb[BB*CC];
__device__ __align__(16) float g_Tre[BB*CC*NF];
__device__ __align__(16) float g_Tim[BB*CC*NF];
__device__ __align__(16) float g_Xre[BB*CC*NF];
__device__ __align__(16) float g_Xim[BB*CC*NF];
__device__ __align__(16) float g_xfft[BB*CC*NN];
__device__ __align__(16) float g_mid[BB*60*NN];
__device__ __align__(16) float g_y2[BB*CC*NN];
__device__ float g_gap[BB*CC];
__device__ float g_eca[BB*CC];
__device__ float g_dk[BB*PD*9];
__device__ __align__(16) float g_att16[BB*PD*NN];
__device__ __align__(16) float g_xm[BB*NN*CC];
__device__ __align__(16) float g_t[(size_t)BB*H2V*NN];
__device__ __align__(16) float g_act[(size_t)BB*HIDV*NN];
__device__ __align__(16) float g_bwT[3*CC*CC];
__device__ __align__(16) float g_aggrT[CC*CC];
__device__ __align__(16) float g_fc1T[CC*H2V];
__device__ __align__(16) float g_fc2T[HIDV*CC];
__device__ __align__(16) float g_w1t[60*CC*9];
__device__ __align__(16) float g_w2t[CC*60*9];

__device__ __forceinline__ float gelu_exact(float a){
    return 0.5f*a*(1.f+erff(a*0.70710678118654752f));
}
__device__ __forceinline__ float sigm(float a){ return 1.f/(1.f+expf(-a)); }

__device__ __forceinline__ int bandof(int fy, int fx){
    float yy = -1.f + (float)fy*(2.f/95.f);
    float xv = (float)fx*(1.f/48.f);
    float rr = sqrtf(yy*yy+xv*xv);
    return rr<=0.25f ? 0 : (rr<=0.6f ? 1 : 2);
}

/* ---------- weight reshapes (once per launch, cheap) ---------- */
__global__ void k_transpose(const float* bw, const float* aw,
                            const float* f1, const float* f2,
                            const float* cw1, const float* cw2){
    int i = blockIdx.x*blockDim.x + threadIdx.x;
    if (i < 3*CC*CC){ int k=i/(CC*CC); int r=i%(CC*CC); int d=r/CC, c=r%CC;
        g_bwT[(k*CC+c)*CC+d] = bw[i]; }
    if (i < CC*CC){ int d=i/CC, c=i%CC; g_aggrT[c*CC+d]=aw[i]; }
    if (i < H2V*CC){ int d=i/CC, c=i%CC; g_fc1T[c*H2V+d]=f1[i]; }
    if (i < CC*HIDV){ int d=i/HIDV, h=i%HIDV; g_fc2T[h*CC+d]=f2[i]; }
    if (i < 60*CC*9){ int o=i/(CC*9); int r=i%(CC*9); int ic=r/9, tap=r%9;
        g_w1t[(ic*9+tap)*60+o] = cw1[i]; }
    if (i < CC*60*9){ int oc=i/(60*9); int r=i%(60*9); int ic=r/9, tap=r%9;
        g_w2t[(ic*9+tap)*CC+oc] = cw2[i]; }
}

/* ---------- LN1: 32-row tiles, coalesced transpose store ---------- */
__global__ void k_ln1(const float* __restrict__ x, const float* __restrict__ gw,
                      const float* __restrict__ bw){
    int blk = blockIdx.x;
    int b = (blk*32)/NN, n0 = (blk*32)%NN;
    __shared__ float s[180*33];
    __shared__ float mean_[32], rinv_[32];
    int t = threadIdx.x;
    const float* xb = x + ((size_t)b*NN + n0)*CC;
    for (int i=t;i<32*180;i+=256){
        int r=i/180, c=i%180;
        s[c*33+r] = xb[(size_t)r*CC + c];
    }
    __syncthreads();
    int wid=t>>5, lane=t&31;
    for (int r=wid;r<32;r+=8){
        float su=0.f, q=0.f;
        for (int c=lane;c<180;c+=32){ float v=s[c*33+r]; su+=v; q+=v*v; }
        for (int off=16;off;off>>=1){
            su += __shfl_xor_sync(0xffffffffu,su,off);
            q  += __shfl_xor_sync(0xffffffffu,q,off);
        }
        if (lane==0){
            float m = su/180.f;
            mean_[r]=m;
            rinv_[r]=rsqrtf(q/180.f - m*m + EPS_C);
        }
    }
    __syncthreads();
    for (int i=t;i<180*32;i+=256){
        int c=i/32, r=i&31;
        g_ximg[((size_t)(b*CC+c))*NN + n0 + r] =
            (s[c*33+r]-mean_[r])*rinv_[r]*gw[c] + bw[c];
    }
}

__global__ void k_chanmean(int which){
    int bc = blockIdx.x;
    const float* src = (which ? g_y2 : g_ximg) + (size_t)bc*NN;
    __shared__ float s[256];
    float acc = 0.f;
    for (int i=threadIdx.x; i<NN; i+=256) acc += src[i];
    s[threadIdx.x] = acc;
    __syncthreads();
    for (int st=128; st>0; st>>=1){
        if (threadIdx.x<st) s[threadIdx.x]+=s[threadIdx.x+st];
        __syncthreads();
    }
    if (threadIdx.x==0){
        float m = s[0]/(float)NN;
        if (which) g_gap[bc]=m; else g_cmean[bc]=m;
    }
}

/* ---------- gates: one warp per gate, shuffle reduce ---------- */
__global__ void k_gates(const float* __restrict__ gw, const float* __restrict__ gb,
                        const float* __restrict__ bb){
    int b = blockIdx.x;
    __shared__ float sg[3];
    int t = threadIdx.x;
    int g = t>>5, lane = t&31;
    if (g < 3){
        float a = 0.f;
        for (int c=lane;c<CC;c+=32) a += g_cmean[b*CC+c]*gw[g*CC+c];
        for (int off=16;off;off>>=1) a += __shfl_xor_sync(0xffffffffu,a,off);
        if (lane==0) sg[g] = sigm(a + gb[g]);
    }
    __syncthreads();
    if (t==0){
        float m = fmaxf(sg[0], fmaxf(sg[1], sg[2]));
        float e0=expf(sg[0]-m), e1=expf(sg[1]-m), e2=expf(sg[2]-m);
        float su = e0+e1+e2;
        sg[0]=e0/su; sg[1]=e1/su; sg[2]=e2/su;
        g_gates[b*3+0]=sg[0]; g_gates[b*3+1]=sg[1]; g_gates[b*3+2]=sg[2];
    }
    __syncthreads();
    if (t < CC)
        g_bb[b*CC+t] = sg[0]*bb[t] + sg[1]*bb[CC+t] + sg[2]*bb[2*CC+t];
}

/* ---------- forward row rDFT: 8-row register tiles ---------- */
__global__ void k_rowdft(){
    int bc = blockIdx.x;
    __shared__ float img[NN];
    __shared__ float twr[96], twi[96];
    int t = threadIdx.x;
    const float* src = g_ximg + (size_t)bc*NN;
    for (int i=t;i<NN;i+=256) img[i]=src[i];
    if (t<96){ float s,c; sincospif((float)t*(1.f/48.f), &s,&c); twr[t]=c; twi[t]=-s; }
    __syncthreads();
    float* Tr = g_Tre + (size_t)bc*NF;
    float* Ti = g_Tim + (size_t)bc*NF;
    for (int tile=t; tile<588; tile+=256){
        int r0 = (tile/49)*8, fx = tile%49;
        float ar[8], ai[8];
        #pragma unroll
        for (int i=0;i<8;i++){ ar[i]=0.f; ai[i]=0.f; }
        int k=0;
        for (int xq=0; xq<96; xq++){
            float c=twr[k], s=twi[k];
            #pragma unroll
            for (int i=0;i<8;i++){
                float v = img[(r0+i)*96 + xq];
                ar[i] += v*c; ai[i] += v*s;
            }
            k += fx; if (k>=96) k-=96;
        }
        #pragma unroll
        for (int i=0;i<8;i++){ Tr[(r0+i)*49+fx]=ar[i]; Ti[(r0+i)*49+fx]=ai[i]; }
    }
}

/* ---------- column DFT radix-2 DIT, forward (inv=0) / inverse (inv=1) ---- */
__global__ void k_cdft(int inv){
    int bc = blockIdx.x;
    __shared__ float Sr[NF], Si[NF];
    __shared__ float twr[96], twi[96];
    int t = threadIdx.x;
    const float* sr = g_Tre + (size_t)bc*NF;
    const float* si = g_Tim + (size_t)bc*NF;
    for (int i=t;i<NF;i+=256){ Sr[i]=sr[i]; Si[i]=si[i]; }
    if (t<96){ float s,c; sincospif((float)t*(1.f/48.f), &s,&c);
        twr[t]=c; twi[t]= inv ? s : -s; }
    __syncthreads();
    float* Xr = g_Xre + (size_t)bc*NF;
    float* Xi = g_Xim + (size_t)bc*NF;
    for (int tile=t; tile<336; tile+=256){
        int fy = tile/7, fx0 = (tile%7)*7;
        float Er[7],Ei[7],Or[7],Oi[7];
        #pragma unroll
        for (int j=0;j<7;j++){ Er[j]=0.f;Ei[j]=0.f;Or[j]=0.f;Oi[j]=0.f; }
        int k = 0;
        int step = (2*fy)%96;
        for (int m=0;m<48;m++){
            float c=twr[k], s=twi[k];
            const float* er_=&Sr[(2*m)*49+fx0];
            const float* ei_=&Si[(2*m)*49+fx0];
            const float* or_=&Sr[(2*m+1)*49+fx0];
            const float* oi_=&Si[(2*m+1)*49+fx0];
            #pragma unroll
            for (int j=0;j<7;j++){
                float vr=er_[j], vi=ei_[j];
                Er[j] += vr*c - vi*s;
                Ei[j] += vr*s + vi*c;
                float wr=or_[j], wi=oi_[j];
                Or[j] += wr*c - wi*s;
                Oi[j] += wr*s + wi*c;
            }
            k += step; if (k>=96) k-=96;
        }
        float wc=twr[fy], wsn=twi[fy];
        #pragma unroll
        for (int j=0;j<7;j++){
            float tr = Or[j]*wc - Oi[j]*wsn;
            float ti = Or[j]*wsn + Oi[j]*wc;
            int oA = fy*49+fx0+j, oB = (fy+48)*49+fx0+j;
            Xr[oA]=Er[j]+tr; Xi[oA]=Ei[j]+ti;
            Xr[oB]=Er[j]-tr; Xi[oB]=Ei[j]-ti;
        }
    }
}

/* ---------- frequency-domain banded channel matmul, float4 loads ---------- */
__global__ void k_freqmm(){
    int bx = blockIdx.x; int b=bx/96, fy=bx%96;
    __shared__ __align__(16) float xsr[180*8], xsi[180*8];
    int t = threadIdx.x;
    int pos = 0;
    while (pos < 49){
        int k0 = bandof(fy,pos);
        int len = 1;
        while (pos+len<49 && len<8 && bandof(fy,pos+len)==k0) len++;
        __syncthreads();
        for (int i=t;i<len*180;i+=192){
            int c=i/len, u=i-c*len;
            size_t src = ((size_t)(b*CC+c))*NF + fy*49 + pos + u;
            xsr[c*8+u]=g_Xre[src];
            xsi[c*8+u]=g_Xim[src];
        }
        __syncthreads();
        if (t < 180){
            float ar[8], ai[8];
            #pragma unroll
            for (int u=0;u<8;u++){ ar[u]=0.f; ai[u]=0.f; }
            const float* Wp = &g_bwT[k0*CC*CC];
            for (int c=0;c<180;c++){
                float w = Wp[c*180+t];
                float4 r0 = *(const float4*)&xsr[c*8];
                float4 r1 = *(const float4*)&xsr[c*8+4];
                float4 i0 = *(const float4*)&xsi[c*8];
                float4 i1 = *(const float4*)&xsi[c*8+4];
                ar[0]+=w*r0.x; ar[1]+=w*r0.y; ar[2]+=w*r0.z; ar[3]+=w*r0.w;
                ar[4]+=w*r1.x; ar[5]+=w*r1.y; ar[6]+=w*r1.z; ar[7]+=w*r1.w;
                ai[0]+=w*i0.x; ai[1]+=w*i0.y; ai[2]+=w*i0.z; ai[3]+=w*i0.w;
                ai[4]+=w*i1.x; ai[5]+=w*i1.y; ai[6]+=w*i1.z; ai[7]+=w*i1.w;
            }
            float gk = g_gates[b*3+k0];
            for (int u=0;u<len;u++){
                size_t o = ((size_t)(b*CC+t))*NF + fy*49 + pos + u;
                g_Tre[o]=gk*ar[u];
                g_Tim[o]=gk*ai[u];
            }
        }
        pos += len;
    }
}

/* ---------- inverse row rDFT + residual : (x, x+48) even/odd pairing ----
   tw[(x+48)fx] = tw[x·fx]·(−1)^fx  ⇒ out(x)=u0±u48+2(aE+aO),
   out(x+48)=u0±u48+2(aE−aO); same u48 sign (48 even).                   */
__global__ void k_irow(){
    int bc = blockIdx.x;
    __shared__ float ur[NF], ui[NF];
    __shared__ float twr[96], twi[96];
    int t = threadIdx.x;
    const float* Ur = g_Xre + (size_t)bc*NF;
    const float* Ui = g_Xim + (size_t)bc*NF;
    for (int i=t;i<NF;i+=256){ ur[i]=Ur[i]; ui[i]=Ui[i]; }
    if (t<96){ float s,c; sincospif((float)t*(1.f/48.f), &s,&c); twr[t]=c; twi[t]=s; }
    __syncthreads();
    float bbv = g_bb[bc];
    for (int tile=t; tile<576; tile+=256){
        int y0 = (tile/48)*8;
        int xp = tile%48;
        float aE[8], aO[8];
        #pragma unroll
        for (int i=0;i<8;i++){ aE[i]=0.f; aO[i]=0.f; }
        int k = xp;   /* k = (xp*fx)%96, fx starts at 1 */
        for (int fx=1; fx<48; fx+=2){
            /* fx odd */
            {
                float c=twr[k], s=twi[k];
                #pragma unroll
                for (int i=0;i<8;i++){
                    float vr=ur[(y0+i)*49+fx], vi=ui[(y0+i)*49+fx];
                    aO[i] += vr*c - vi*s;
                }
                k += xp; if (k>=96) k-=96;
            }
            /* fx+1 even (skip when fx==47) */
            if (fx+1 < 48){
                float c=twr[k], s=twi[k];
                #pragma unroll
                for (int i=0;i<8;i++){
                    float vr=ur[(y0+i)*49+fx+1], vi=ui[(y0+i)*49+fx+1];
                    aE[i] += vr*c - vi*s;
                }
                k += xp; if (k>=96) k-=96;
            }
        }
        float sgn = (xp&1) ? -1.f : 1.f;
        #pragma unroll
        for (int i=0;i<8;i++){
            float u0  = ur[(y0+i)*49];
            float u48 = sgn*ur[(y0+i)*49+48];
            float vA = (u0 + u48 + 2.f*(aE[i]+aO[i]))*(1.f/9216.f);
            float vB = (u0 + u48 + 2.f*(aE[i]-aO[i]))*(1.f/9216.f);
            size_t row = (size_t)bc*NN + (y0+i)*96;
            g_xfft[row+xp]    = g_ximg[row+xp]    + FFT_RES_C*(vA + bbv);
            g_xfft[row+xp+48] = g_ximg[row+xp+48] + FFT_RES_C*(vB + bbv);
        }
    }
}

/* ---------- CAB conv1 180->60 3x3 + GELU : 4px x 16oc tiles, float4 weights ---------- */
__global__ void k_conv1(const float* __restrict__ bias){
    int bi = blockIdx.x; int b = bi/36; int tile = bi%36;
    int ty0 = (tile/6)*16, tx0 = (tile%6)*16;
    __shared__ float ins[12*324];
    __shared__ __align__(16) float ws[12*9*64];
    int t = threadIdx.x;
    int oid = t>>6;
    int pxid = t&63;
    int px0 = (pxid&7)*2, py0 = (pxid>>3)*2;
    float acc[16][4];
    #pragma unroll
    for (int j=0;j<16;j++){ acc[j][0]=0.f;acc[j][1]=0.f;acc[j][2]=0.f;acc[j][3]=0.f; }
    for (int ic0=0; ic0<180; ic0+=12){
        __syncthreads();
        for (int i=t;i<12*324;i+=256){
            int icl=i/324, r=i%324; int hy=r/18, hx=r%18;
            int gy=ty0+hy-1, gx=tx0+hx-1;
            float v=0.f;
            if (gy>=0 && gy<96 && gx>=0 && gx<96)
                v = g_xfft[((size_t)(b*CC+ic0+icl))*NN + gy*96+gx];
            ins[i]=v;
        }
        for (int i=t;i<6912;i+=256){
            int q=i>>6, o=i&63;
            ws[i] = (o<60) ? g_w1t[ic0*540 + q*60 + o] : 0.f;
        }
        __syncthreads();
        for (int icl=0; icl<12; icl++){
            #pragma unroll
            for (int tap=0;tap<9;tap++){
                int dy=tap/3, dx=tap%3;
                int base = icl*324 + (py0+dy)*18 + (px0+dx);
                float v0=ins[base], v1=ins[base+1], v2=ins[base+18], v3=ins[base+19];
                const float4* wp4 = (const float4*)&ws[(icl*9+tap)*64 + oid*16];
                float4 wa=wp4[0], wb=wp4[1], wcc=wp4[2], wd=wp4[3];
                float wv[16]={wa.x,wa.y,wa.z,wa.w, wb.x,wb.y,wb.z,wb.w,
                              wcc.x,wcc.y,wcc.z,wcc.w, wd.x,wd.y,wd.z,wd.w};
                #pragma unroll
                for (int j=0;j<16;j++){
                    float w = wv[j];
                    acc[j][0]+=w*v0; acc[j][1]+=w*v1;
                    acc[j][2]+=w*v2; acc[j][3]+=w*v3;
                }
            }
        }
    }
    #pragma unroll
    for (int j=0;j<16;j++){
        int o = oid*16+j;
        if (o < 60){
            float bv = bias[o];
            #pragma unroll
            for (int p=0;p<4;p++){
                int n = (ty0+py0+(p>>1))*96 + tx0+px0+(p&1);
                g_mid[((size_t)(b*60+o))*NN + n] = gelu_exact(acc[j][p]+bv);
            }
        }
    }
}

/* ---------- CAB conv2 60->180 3x3 : 4px x 16oc tiles, float4 weights ---------- */
__global__ void k_conv2(const float* __restrict__ bias){
    int bx = blockIdx.x;
    int b = bx/108; int r = bx%108; int tile = r/3; int oc0 = (r%3)*60;
    int ty0 = (tile/6)*16, tx0 = (tile%6)*16;
    __shared__ float ins[12*324];
    __shared__ __align__(16) float ws[12*9*64];
    int t = threadIdx.x;
    int oid = t>>6;
    int pxid = t&63;
    int px0 = (pxid&7)*2, py0 = (pxid>>3)*2;
    float acc[16][4];
    #pragma unroll
    for (int j=0;j<16;j++){ acc[j][0]=0.f;acc[j][1]=0.f;acc[j][2]=0.f;acc[j][3]=0.f; }
    for (int ic0=0; ic0<60; ic0+=12){
        __syncthreads();
        for (int i=t;i<12*324;i+=256){
            int icl=i/324, rr=i%324; int hy=rr/18, hx=rr%18;
            int gy=ty0+hy-1, gx=tx0+hx-1;
            float v=0.f;
            if (gy>=0 && gy<96 && gx>=0 && gx<96)
                v = g_mid[((size_t)(b*60+ic0+icl))*NN + gy*96+gx];
            ins[i]=v;
        }
        for (int i=t;i<6912;i+=256){
            int q=i>>6, o=i&63;
            ws[i] = (o<60) ? g_w2t[(ic0*9+q)*CC + oc0 + o] : 0.f;
        }
        __syncthreads();
        for (int icl=0; icl<12; icl++){
            #pragma unroll
            for (int tap=0;tap<9;tap++){
                int dy=tap/3, dx=tap%3;
                int base = icl*324 + (py0+dy)*18 + (px0+dx);
                float v0=ins[base], v1=ins[base+1], v2=ins[base+18], v3=ins[base+19];
                const float4* wp4 = (const float4*)&ws[(icl*9+tap)*64 + oid*16];
                float4 wa=wp4[0], wb=wp4[1], wcc=wp4[2], wd=wp4[3];
                float wv[16]={wa.x,wa.y,wa.z,wa.w, wb.x,wb.y,wb.z,wb.w,
                              wcc.x,wcc.y,wcc.z,wcc.w, wd.x,wd.y,wd.z,wd.w};
                #pragma unroll
                for (int j=0;j<16;j++){
                    float w = wv[j];
                    acc[j][0]+=w*v0; acc[j][1]+=w*v1;
                    acc[j][2]+=w*v2; acc[j][3]+=w*v3;
                }
            }
        }
    }
    #pragma unroll
    for (int j=0;j<16;j++){
        int ol = oid*16+j;
        if (ol < 60){
            int o = oc0 + ol;
            float bv = bias[o];
            #pragma unroll
            for (int p=0;p<4;p++){
                int n = (ty0+py0+(p>>1))*96 + tx0+px0+(p&1);
                g_y2[((size_t)(b*CC+o))*NN + n] = acc[j][p]+bv;
            }
        }
    }
}

__global__ void k_eca(const float* __restrict__ ew){
    int b = blockIdx.x; int c = threadIdx.x;
    if (c < CC){
        float z = 0.f;
        for (int i=0;i<5;i++){
            int idx=c-2+i;
            if (idx>=0 && idx<CC) z += g_gap[b*CC+idx]*ew[i];
        }
        g_eca[b*CC+c] = sigm(z);
    }
}

__global__ void k_dwc(const float* __restrict__ w1, const float* __restrict__ b1,
                      const float* __restrict__ w2, const float* __restrict__ b2){
    int b = blockIdx.x; int t = threadIdx.x;
    __shared__ float hdn[8];
    if (t < 8){
        float a = b1[t];
        for (int p=0;p<16;p++) a += g_cmean[b*CC+p]*w1[t*16+p];
        hdn[t] = gelu_exact(a);
    }
    __syncthreads();
    if (t < 144){
        float a = b2[t];
        for (int o=0;o<8;o++) a += hdn[o]*w2[t*8+o];
        g_dk[b*144+t] = a;
    }
}

/* ---------- 13x13 LK + dynamic 3x3 : 2x2px x 4oc tiles, smem weights ---------- */
__global__ void k_lkdyn(const float* __restrict__ plk){
    int bi = blockIdx.x; int b = bi/36; int tile = bi%36;
    int ty0 = (tile/6)*16, tx0 = (tile%6)*16;
    __shared__ float ins[28*28];
    __shared__ float wlk[16*169];
    __shared__ float dks[144];
    int t = threadIdx.x;
    int ocg = t>>6; int pxid = t&63;
    int px0=(pxid&7)*2, py0=(pxid>>3)*2;
    if (t < 144) dks[t]=g_dk[b*144+t];
    float acc[4][4];
    #pragma unroll
    for (int j=0;j<4;j++){ acc[j][0]=0.f;acc[j][1]=0.f;acc[j][2]=0.f;acc[j][3]=0.f; }
    for (int ic=0; ic<16; ic++){
        __syncthreads();
        for (int i=t;i<784;i+=256){
            int hy=i/28, hx=i%28;
            int gy=ty0+hy-6, gx=tx0+hx-6;
            float v=0.f;
            if (gy>=0 && gy<96 && gx>=0 && gx<96)
                v = g_ximg[((size_t)(b*CC+ic))*NN + gy*96+gx];
            ins[i]=v;
        }
        for (int i=t;i<2704;i+=256){
            int oc=i/169, tap=i%169;
            wlk[i] = plk[(oc*16+ic)*169 + tap];
        }
        __syncthreads();
        for (int ky=0;ky<13;ky++){
            #pragma unroll
            for (int kx=0;kx<13;kx++){
                int base = (py0+ky)*28 + px0+kx;
                float v0=ins[base], v1=ins[base+1], v2=ins[base+28], v3=ins[base+29];
                #pragma unroll
                for (int j=0;j<4;j++){
                    float wv = wlk[(ocg*4+j)*169 + ky*13+kx];
                    acc[j][0]+=wv*v0; acc[j][1]+=wv*v1;
                    acc[j][2]+=wv*v2; acc[j][3]+=wv*v3;
                }
            }
        }
        if ((ic>>2)==ocg){
            int j = ic&3;
            #pragma unroll
            for (int tap=0;tap<9;tap++){
                int dy=tap/3, dx=tap%3;
                int base=(py0+5+dy)*28 + px0+5+dx;
                float wv = dks[ic*9+tap];
                acc[j][0]+=wv*ins[base];   acc[j][1]+=wv*ins[base+1];
                acc[j][2]+=wv*ins[base+28];acc[j][3]+=wv*ins[base+29];
            }
        }
    }
    #pragma unroll
    for (int j=0;j<4;j++){
        int oc = ocg*4+j;
        #pragma unroll
        for (int p=0;p<4;p++){
            int n = (ty0+py0+(p>>1))*96 + tx0+px0+(p&1);
            g_att16[((size_t)(b*16+oc))*NN + n] = acc[j][p];
        }
    }
}

/* ---------- aggr 1x1 + residual assembly : 4d x 8px float4 tiles ---------- */
__global__ void k_xm(const float* __restrict__ x, const float* __restrict__ ab){
    int bi = blockIdx.x; int b = bi/288; int n0 = (bi%288)*32;
    __shared__ __align__(16) float us[180*32];
    int t = threadIdx.x;
    for (int i=t;i<180*32;i+=192){
        int c=i>>5, p=i&31;
        float v = (c<16) ? g_att16[((size_t)(b*16+c))*NN + n0+p]
                         : g_ximg [((size_t)(b*CC+c))*NN + n0+p];
        us[i]=v;
    }
    __syncthreads();
    int dq=t>>2, pq=t&3;
    float acc[8][4];
    if (dq < 45){
        int d0 = dq*4;
        #pragma unroll
        for (int p=0;p<8;p++){
            acc[p][0]=ab[d0]; acc[p][1]=ab[d0+1];
            acc[p][2]=ab[d0+2]; acc[p][3]=ab[d0+3];
        }
        for (int c=0;c<180;c++){
            float4 w  = *(const float4*)&g_aggrT[c*180 + d0];
            float4 xa = *(const float4*)&us[c*32 + pq*8];
            float4 xb = *(const float4*)&us[c*32 + pq*8 + 4];
            float xv[8] = {xa.x,xa.y,xa.z,xa.w, xb.x,xb.y,xb.z,xb.w};
            #pragma unroll
            for (int p=0;p<8;p++){
                acc[p][0] += w.x*xv[p];
                acc[p][1] += w.y*xv[p];
                acc[p][2] += w.z*xv[p];
                acc[p][3] += w.w*xv[p];
            }
        }
        #pragma unroll
        for (int j=0;j<4;j++){
            float e = g_eca[b*180+d0+j];
            const float* yp = &g_y2[((size_t)(b*180+d0+j))*NN + n0 + pq*8];
            float4 ya = *(const float4*)yp;
            float4 yb = *(const float4*)(yp+4);
            float yv[8]={ya.x,ya.y,ya.z,ya.w, yb.x,yb.y,yb.z,yb.w};
            #pragma unroll
            for (int p=0;p<8;p++) acc[p][j] += CONV_SCALE_C*e*yv[p];
        }
    }
    __syncthreads();
    if (dq < 45){
        int d0 = dq*4;
        #pragma unroll
        for (int p=0;p<8;p++){
            #pragma unroll
            for (int j=0;j<4;j++)
                us[(pq*8+p)*180 + d0+j] = acc[p][j];
        }
    }
    __syncthreads();
    for (int i=t;i<32*180;i+=192){
        size_t idx = ((size_t)(b*NN)+n0+(i/180))*CC + (i%180);
        g_xm[idx] = x[idx] + us[i];
    }
}

/* ---------- LN2 + fc1, 4d x 8px register tiles + float4 ---------- */
__global__ void k_ln2fc1(const float* __restrict__ g2, const float* __restrict__ b2,
                         const float* __restrict__ fb){
    int bi = blockIdx.x; int b = bi/288; int n0 = (bi%288)*32;
    __shared__ __align__(16) float xs[180*36];
    __shared__ float mean_[32], rinv_[32];
    int t = threadIdx.x;
    for (int i=t;i<32*180;i+=256){
        int p=i/180, c=i%180;
        xs[c*36+p] = g_xm[((size_t)(b*NN)+n0+p)*CC + c];
    }
    __syncthreads();
    int wid=t>>5, lane=t&31;
    for (int r=wid;r<32;r+=8){
        float s=0.f, q=0.f;
        for (int c=lane;c<180;c+=32){ float v=xs[c*36+r]; s+=v; q+=v*v; }
        for (int off=16;off;off>>=1){
            s += __shfl_xor_sync(0xffffffffu,s,off);
            q += __shfl_xor_sync(0xffffffffu,q,off);
        }
        if (lane==0){
            float m = s/180.f;
            mean_[r]=m;
            rinv_[r]=rsqrtf(q/180.f - m*m + EPS_C);
        }
    }
    __syncthreads();
    for (int i=t;i<180*32;i+=256){
        int c=i/32, r=i&31;
        xs[c*36+r] = (xs[c*36+r]-mean_[r])*rinv_[r]*g2[c] + b2[c];
    }
    __syncthreads();
    if (t < 240){
        int dq=t>>2, pq=t&3;
        for (int pass=0;pass<3;pass++){
            int d0 = pass*240 + dq*4;
            float acc[4][8];
            #pragma unroll
            for (int j=0;j<4;j++){
                float bv = fb[d0+j];
                #pragma unroll
                for (int p=0;p<8;p++) acc[j][p]=bv;
            }
            for (int c=0;c<180;c++){
                float4 w  = *(const float4*)&g_fc1T[c*720 + d0];
                float4 xa = *(const float4*)&xs[c*36 + pq*8];
                float4 xb = *(const float4*)&xs[c*36 + pq*8 + 4];
                float xv[8] = {xa.x,xa.y,xa.z,xa.w, xb.x,xb.y,xb.z,xb.w};
                #pragma unroll
                for (int p=0;p<8;p++){
                    acc[0][p] += w.x*xv[p];
                    acc[1][p] += w.y*xv[p];
                    acc[2][p] += w.z*xv[p];
                    acc[3][p] += w.w*xv[p];
                }
            }
            #pragma unroll
            for (int j=0;j<4;j++){
                float* op = &g_t[((size_t)(b*720+d0+j))*NN + n0 + pq*8];
                *(float4*)op     = make_float4(acc[j][0],acc[j][1],acc[j][2],acc[j][3]);
                *(float4*)(op+4) = make_float4(acc[j][4],acc[j][5],acc[j][6],acc[j][7]);
            }
        }
    }
}

/* ---------- depthwise 3x3 + GLU : 32x32 smem tiles, 4px/thread ---------- */
__global__ void k_dwglu(const float* __restrict__ dww, const float* __restrict__ dwb){
    int bx = blockIdx.x;
    int tile = bx%9; int bh = bx/9; int b = bh/HIDV; int h = bh%HIDV;
    int ty0 = (tile/3)*32, tx0 = (tile%3)*32;
    __shared__ float sp[34*34], sg[34*34];
    int t = threadIdx.x;
    const float* tp = g_t + ((size_t)(b*H2V+h))*NN;
    const float* tg = tp + (size_t)HIDV*NN;
    for (int i=t;i<1156;i+=256){
        int hy=i/34, hx=i%34;
        int gy=ty0+hy-1, gx=tx0+hx-1;
        bool ok = (gy>=0 && gy<96 && gx>=0 && gx<96);
        int src = gy*96+gx;
        sp[i] = ok ? tp[src] : 0.f;
        sg[i] = ok ? tg[src] : 0.f;
    }
    float wp[9], wg[9];
    #pragma unroll
    for (int j=0;j<9;j++){ wp[j]=dww[h*9+j]; wg[j]=dww[(h+HIDV)*9+j]; }
    float bp = dwb[h], bg = dwb[h+HIDV];
    __syncthreads();
    int lx = t&31, ly0 = (t>>5)*4;
    float* op = g_act + ((size_t)(b*HIDV+h))*NN;
    #pragma unroll
    for (int q=0;q<4;q++){
        int ly = ly0+q;
        float pa=bp, ga=bg;
        #pragma unroll
        for (int dy=0;dy<3;dy++){
            int base = (ly+dy)*34 + lx;
            pa += wp[dy*3+0]*sp[base]   + wp[dy*3+1]*sp[base+1]   + wp[dy*3+2]*sp[base+2];
            ga += wg[dy*3+0]*sg[base]   + wg[dy*3+1]*sg[base+1]   + wg[dy*3+2]*sg[base+2];
        }
        op[(ty0+ly)*96 + tx0+lx] = pa * (ga*sigm(ga));
    }
}

/* ---------- fc2 + final residual, 4d x 8px tiles + float4 ---------- */
__global__ void k_fc2(const float* __restrict__ fb, float* __restrict__ out){
    int bi = blockIdx.x; int b = bi/288; int n0 = (bi%288)*32;
    __shared__ __align__(16) float sh[360*32];
    int t = threadIdx.x;
    for (int i=t;i<360*32;i+=192){
        int h=i>>5, p=i&31;
        sh[i] = g_act[((size_t)(b*360+h))*NN + n0 + p];
    }
    __syncthreads();
    int dq=t>>2, pq=t&3;
    if (dq < 45){
        int d0 = dq*4;
        float acc[8][4];
        #pragma unroll
        for (int p=0;p<8;p++){
            acc[p][0]=fb[d0]; acc[p][1]=fb[d0+1];
            acc[p][2]=fb[d0+2]; acc[p][3]=fb[d0+3];
        }
        for (int h=0;h<360;h++){
            float4 w  = *(const float4*)&g_fc2T[h*180 + d0];
            float4 xa = *(const float4*)&sh[h*32 + pq*8];
            float4 xb = *(const float4*)&sh[h*32 + pq*8 + 4];
            float xv[8] = {xa.x,xa.y,xa.z,xa.w, xb.x,xb.y,xb.z,xb.w};
            #pragma unroll
            for (int p=0;p<8;p++){
                acc[p][0] += w.x*xv[p];
                acc[p][1] += w.y*xv[p];
                acc[p][2] += w.z*xv[p];
                acc[p][3] += w.w*xv[p];
            }
        }
        #pragma unroll
        for (int p=0;p<8;p++){
            size_t base = ((size_t)(b*NN)+n0+pq*8+p)*CC + d0;
            float4 xm4 = *(const float4*)&g_xm[base];
            float4 o4;
            o4.x = xm4.x + acc[p][0];
            o4.y = xm4.y + acc[p][1];
            o4.z = xm4.z + acc[p][2];
            o4.w = xm4.w + acc[p][3];
            *(float4*)&out[base] = o4;
        }
    }
}

extern "C" void kernel_launch(void* const* d_in, const int* in_sizes, int n_in,
                              void* d_out, int out_size){
    (void)in_sizes; (void)n_in; (void)out_size;
    const float* x      = (const float*)d_in[0];
    const float* ln1_g  = (const float*)d_in[3];
    const float* ln1_b  = (const float*)d_in[4];
    const float* band_w = (const float*)d_in[5];
    const float* band_b = (const float*)d_in[6];
    const float* gate_w = (const float*)d_in[7];
    const float* gate_b = (const float*)d_in[8];
    const float* cab_w1 = (const float*)d_in[9];
    const float* cab_b1 = (const float*)d_in[10];
    const float* cab_w2 = (const float*)d_in[11];
    const float* cab_b2 = (const float*)d_in[12];
    const float* eca_w  = (const float*)d_in[13];
    const float* plk    = (const float*)d_in[14];
    const float* dwc_w1 = (const float*)d_in[15];
    const float* dwc_b1 = (const float*)d_in[16];
    const float* dwc_w2 = (const float*)d_in[17];
    const float* dwc_b2 = (const float*)d_in[18];
    const float* aggr_w = (const float*)d_in[19];
    const float* aggr_b = (const float*)d_in[20];
    const float* ln2_g  = (const float*)d_in[21];
    const float* ln2_b  = (const float*)d_in[22];
    const float* fc1_w  = (const float*)d_in[23];
    const float* fc1_b  = (const float*)d_in[24];
    const float* dw_w   = (const float*)d_in[25];
    const float* dw_b   = (const float*)d_in[26];
    const float* fc2_w  = (const float*)d_in[27];
    const float* fc2_b  = (const float*)d_in[28];
    float* out = (float*)d_out;

    k_transpose<<<512,256>>>(band_w, aggr_w, fc1_w, fc2_w, cab_w1, cab_w2);
    k_ln1<<<BB*NN/32,256>>>(x, ln1_g, ln1_b);
    k_chanmean<<<BB*CC,256>>>(0);
    k_gates<<<BB,192>>>(gate_w, gate_b, band_b);
    k_rowdft<<<BB*CC,256>>>();
    k_cdft<<<BB*CC,256>>>(0);
    k_freqmm<<<BB*96,192>>>();
    k_cdft<<<BB*CC,256>>>(1);
    k_irow<<<BB*CC,256>>>();
    k_conv1<<<BB*36,256>>>(cab_b1);
    k_conv2<<<BB*108,256>>>(cab_b2);
    k_chanmean<<<BB*CC,256>>>(1);
    k_eca<<<BB,192>>>(eca_w);
    k_dwc<<<BB,192>>>(dwc_w1, dwc_b1, dwc_w2, dwc_b2);
    k_lkdyn<<<BB*36,256>>>(plk);
    k_xm<<<BB*288,192>>>(x, aggr_b);
    k_ln2fc1<<<BB*288,256>>>(ln2_g, ln2_b, fc1_b);
    k_dwglu<<<BB*HIDV*9,256>>>(dw_w, dw_b);
    k_fc2<<<BB*288,192>>>(fc2_b, out);
}

// round 16
// speedup vs baseline: 1.0597x; 1.0597x over previous
#include <cuda_runtime.h>
#include <math.h>

#define BB 8
#define HH 96
#define WW 96
#define CC 180
#define NN (HH*WW)
#define WF 49
#define NF (HH*WF)
#define HIDV 360
#define H2V 720
#define PD 16
#define FFT_RES_C 0.15f
#define CONV_SCALE_C 0.01f
#define EPS_C 1e-5f

__device__ __align__(16) float g_ximg[BB*CC*NN];
__device__ float g_cmean[BB*CC];
__device__ float g_gates[BB*3];
__device__ float g_bb[BB*CC];
__device__ __align__(16) float g_Tre[BB*CC*NF];
__device__ __align__(16) float g_Tim[BB*CC*NF];
__device__ __align__(16) float g_Xre[BB*CC*NF];
__device__ __align__(16) float g_Xim[BB*CC*NF];
__device__ __align__(16) float g_xfft[BB*CC*NN];
__device__ __align__(16) float g_mid[BB*60*NN];
__device__ __align__(16) float g_y2[BB*CC*NN];
__device__ float g_gap[BB*CC];
__device__ float g_eca[BB*CC];
__device__ float g_dk[BB*PD*9];
__device__ __align__(16) float g_att16[BB*PD*NN];
__device__ __align__(16) float g_xm[BB*NN*CC];
__device__ __align__(16) float g_t[(size_t)BB*H2V*NN];
__device__ __align__(16) float g_act[(size_t)BB*HIDV*NN];
__device__ __align__(16) float g_bwT[3*CC*CC];
__device__ __align__(16) float g_aggrT[CC*CC];
__device__ __align__(16) float g_fc1T[CC*H2V];
__device__ __align__(16) float g_fc2T[HIDV*CC];
__device__ __align__(16) float g_w1t[60*CC*9];
__device__ __align__(16) float g_w2t[CC*60*9];

__device__ __forceinline__ float gelu_exact(float a){
    return 0.5f*a*(1.f+erff(a*0.70710678118654752f));
}
__device__ __forceinline__ float sigm(float a){ return 1.f/(1.f+expf(-a)); }

__device__ __forceinline__ int bandof(int fy, int fx){
    float yy = -1.f + (float)fy*(2.f/95.f);
    float xv = (float)fx*(1.f/48.f);
    float rr = sqrtf(yy*yy+xv*xv);
    return rr<=0.25f ? 0 : (rr<=0.6f ? 1 : 2);
}

/* ---------- weight reshapes (once per launch, cheap) ---------- */
__global__ void k_transpose(const float* bw, const float* aw,
                            const float* f1, const float* f2,
                            const float* cw1, const float* cw2){
    int i = blockIdx.x*blockDim.x + threadIdx.x;
    if (i < 3*CC*CC){ int k=i/(CC*CC); int r=i%(CC*CC); int d=r/CC, c=r%CC;
        g_bwT[(k*CC+c)*CC+d] = bw[i]; }
    if (i < CC*CC){ int d=i/CC, c=i%CC; g_aggrT[c*CC+d]=aw[i]; }
    if (i < H2V*CC){ int d=i/CC, c=i%CC; g_fc1T[c*H2V+d]=f1[i]; }
    if (i < CC*HIDV){ int d=i/HIDV, h=i%HIDV; g_fc2T[h*CC+d]=f2[i]; }
    if (i < 60*CC*9){ int o=i/(CC*9); int r=i%(CC*9); int ic=r/9, tap=r%9;
        g_w1t[(ic*9+tap)*60+o] = cw1[i]; }
    if (i < CC*60*9){ int oc=i/(60*9); int r=i%(60*9); int ic=r/9, tap=r%9;
        g_w2t[(ic*9+tap)*CC+oc] = cw2[i]; }
}

/* ---------- LN1: 32-row tiles, coalesced transpose store ---------- */
__global__ void k_ln1(const float* __restrict__ x, const float* __restrict__ gw,
                      const float* __restrict__ bw){
    int blk = blockIdx.x;
    int b = (blk*32)/NN, n0 = (blk*32)%NN;
    __shared__ float s[180*33];
    __shared__ float mean_[32], rinv_[32];
    int t = threadIdx.x;
    const float* xb = x + ((size_t)b*NN + n0)*CC;
    for (int i=t;i<32*180;i+=256){
        int r=i/180, c=i%180;
        s[c*33+r] = xb[(size_t)r*CC + c];
    }
    __syncthreads();
    int wid=t>>5, lane=t&31;
    for (int r=wid;r<32;r+=8){
        float su=0.f, q=0.f;
        for (int c=lane;c<180;c+=32){ float v=s[c*33+r]; su+=v; q+=v*v; }
        for (int off=16;off;off>>=1){
            su += __shfl_xor_sync(0xffffffffu,su,off);
            q  += __shfl_xor_sync(0xffffffffu,q,off);
        }
        if (lane==0){
            float m = su/180.f;
            mean_[r]=m;
            rinv_[r]=rsqrtf(q/180.f - m*m + EPS_C);
        }
    }
    __syncthreads();
    for (int i=t;i<180*32;i+=256){
        int c=i/32, r=i&31;
        g_ximg[((size_t)(b*CC+c))*NN + n0 + r] =
            (s[c*33+r]-mean_[r])*rinv_[r]*gw[c] + bw[c];
    }
}

__global__ void k_chanmean(int which){
    int bc = blockIdx.x;
    const float* src = (which ? g_y2 : g_ximg) + (size_t)bc*NN;
    __shared__ float s[256];
    float acc = 0.f;
    for (int i=threadIdx.x; i<NN; i+=256) acc += src[i];
    s[threadIdx.x] = acc;
    __syncthreads();
    for (int st=128; st>0; st>>=1){
        if (threadIdx.x<st) s[threadIdx.x]+=s[threadIdx.x+st];
        __syncthreads();
    }
    if (threadIdx.x==0){
        float m = s[0]/(float)NN;
        if (which) g_gap[bc]=m; else g_cmean[bc]=m;
    }
}

/* ---------- gates: one warp per gate, shuffle reduce ---------- */
__global__ void k_gates(const float* __restrict__ gw, const float* __restrict__ gb,
                        const float* __restrict__ bb){
    int b = blockIdx.x;
    __shared__ float sg[3];
    int t = threadIdx.x;
    int g = t>>5, lane = t&31;
    if (g < 3){
        float a = 0.f;
        for (int c=lane;c<CC;c+=32) a += g_cmean[b*CC+c]*gw[g*CC+c];
        for (int off=16;off;off>>=1) a += __shfl_xor_sync(0xffffffffu,a,off);
        if (lane==0) sg[g] = sigm(a + gb[g]);
    }
    __syncthreads();
    if (t==0){
        float m = fmaxf(sg[0], fmaxf(sg[1], sg[2]));
        float e0=expf(sg[0]-m), e1=expf(sg[1]-m), e2=expf(sg[2]-m);
        float su = e0+e1+e2;
        sg[0]=e0/su; sg[1]=e1/su; sg[2]=e2/su;
        g_gates[b*3+0]=sg[0]; g_gates[b*3+1]=sg[1]; g_gates[b*3+2]=sg[2];
    }
    __syncthreads();
    if (t < CC)
        g_bb[b*CC+t] = sg[0]*bb[t] + sg[1]*bb[CC+t] + sg[2]*bb[2*CC+t];
}

/* ---------- forward row rDFT: input folding + 8-row register tiles ----
   tw[(x+48)fx] = tw[x·fx]·(−1)^fx  ⇒
   X[fx] = Σ_{x<48} (v[x] + (−1)^fx v[x+48])·tw[x·fx] — 48 terms, not 96. */
__global__ void k_rowdft(){
    int bc = blockIdx.x;
    __shared__ float img[NN];
    __shared__ float twr[96], twi[96];
    int t = threadIdx.x;
    const float* src = g_ximg + (size_t)bc*NN;
    for (int i=t;i<NN;i+=256) img[i]=src[i];
    if (t<96){ float s,c; sincospif((float)t*(1.f/48.f), &s,&c); twr[t]=c; twi[t]=-s; }
    __syncthreads();
    /* in-place fold: img[row][x] = v[x]+v[x+48], img[row][48+x] = v[x]-v[x+48] */
    for (int i=t;i<96*48;i+=256){
        int row=i/48, xq=i%48;
        int ia = row*96+xq, ib = ia+48;
        float a = img[ia], bq = img[ib];
        img[ia] = a+bq;
        img[ib] = a-bq;
    }
    __syncthreads();
    float* Tr = g_Tre + (size_t)bc*NF;
    float* Ti = g_Tim + (size_t)bc*NF;
    for (int tile=t; tile<588; tile+=256){
        int r0 = (tile/49)*8, fx = tile%49;
        int base = (fx&1) ? 48 : 0;
        float ar[8], ai[8];
        #pragma unroll
        for (int i=0;i<8;i++){ ar[i]=0.f; ai[i]=0.f; }
        int k=0;
        for (int xq=0; xq<48; xq++){
            float c=twr[k], s=twi[k];
            #pragma unroll
            for (int i=0;i<8;i++){
                float v = img[(r0+i)*96 + base + xq];
                ar[i] += v*c; ai[i] += v*s;
            }
            k += fx; if (k>=96) k-=96;
        }
        #pragma unroll
        for (int i=0;i<8;i++){ Tr[(r0+i)*49+fx]=ar[i]; Ti[(r0+i)*49+fx]=ai[i]; }
    }
}

/* ---------- column DFT radix-2 DIT, forward (inv=0) / inverse (inv=1) ---- */
__global__ void k_cdft(int inv){
    int bc = blockIdx.x;
    __shared__ float Sr[NF], Si[NF];
    __shared__ float twr[96], twi[96];
    int t = threadIdx.x;
    const float* sr = g_Tre + (size_t)bc*NF;
    const float* si = g_Tim + (size_t)bc*NF;
    for (int i=t;i<NF;i+=256){ Sr[i]=sr[i]; Si[i]=si[i]; }
    if (t<96){ float s,c; sincospif((float)t*(1.f/48.f), &s,&c);
        twr[t]=c; twi[t]= inv ? s : -s; }
    __syncthreads();
    float* Xr = g_Xre + (size_t)bc*NF;
    float* Xi = g_Xim + (size_t)bc*NF;
    for (int tile=t; tile<336; tile+=256){
        int fy = tile/7, fx0 = (tile%7)*7;
        float Er[7],Ei[7],Or[7],Oi[7];
        #pragma unroll
        for (int j=0;j<7;j++){ Er[j]=0.f;Ei[j]=0.f;Or[j]=0.f;Oi[j]=0.f; }
        int k = 0;
        int step = (2*fy)%96;
        for (int m=0;m<48;m++){
            float c=twr[k], s=twi[k];
            const float* er_=&Sr[(2*m)*49+fx0];
            const float* ei_=&Si[(2*m)*49+fx0];
            const float* or_=&Sr[(2*m+1)*49+fx0];
            const float* oi_=&Si[(2*m+1)*49+fx0];
            #pragma unroll
            for (int j=0;j<7;j++){
                float vr=er_[j], vi=ei_[j];
                Er[j] += vr*c - vi*s;
                Ei[j] += vr*s + vi*c;
                float wr=or_[j], wi=oi_[j];
                Or[j] += wr*c - wi*s;
                Oi[j] += wr*s + wi*c;
            }
            k += step; if (k>=96) k-=96;
        }
        float wc=twr[fy], wsn=twi[fy];
        #pragma unroll
        for (int j=0;j<7;j++){
            float tr = Or[j]*wc - Oi[j]*wsn;
            float ti = Or[j]*wsn + Oi[j]*wc;
            int oA = fy*49+fx0+j, oB = (fy+48)*49+fx0+j;
            Xr[oA]=Er[j]+tr; Xi[oA]=Ei[j]+ti;
            Xr[oB]=Er[j]-tr; Xi[oB]=Ei[j]-ti;
        }
    }
}

/* ---------- frequency-domain banded channel matmul ---------- */
__global__ void k_freqmm(){
    int bx = blockIdx.x; int b=bx/96, fy=bx%96;
    __shared__ __align__(16) float xsr[180*8], xsi[180*8];
    int t = threadIdx.x;
    int pos = 0;
    while (pos < 49){
        int k0 = bandof(fy,pos);
        int len = 1;
        while (pos+len<49 && len<8 && bandof(fy,pos+len)==k0) len++;
        __syncthreads();
        for (int i=t;i<len*180;i+=192){
            int c=i/len, u=i-c*len;
            size_t src = ((size_t)(b*CC+c))*NF + fy*49 + pos + u;
            xsr[c*8+u]=g_Xre[src];
            xsi[c*8+u]=g_Xim[src];
        }
        __syncthreads();
        if (t < 180){
            float ar[8], ai[8];
            #pragma unroll
            for (int u=0;u<8;u++){ ar[u]=0.f; ai[u]=0.f; }
            const float* Wp = &g_bwT[k0*CC*CC];
            for (int c=0;c<180;c++){
                float w = Wp[c*180+t];
                #pragma unroll
                for (int u=0;u<8;u++){
                    ar[u] += w*xsr[c*8+u];
                    ai[u] += w*xsi[c*8+u];
                }
            }
            float gk = g_gates[b*3+k0];
            for (int u=0;u<len;u++){
                size_t o = ((size_t)(b*CC+t))*NF + fy*49 + pos + u;
                g_Tre[o]=gk*ar[u];
                g_Tim[o]=gk*ai[u];
            }
        }
        pos += len;
    }
}

/* ---------- inverse row rDFT + residual ---------- */
__global__ void k_irow(){
    int bc = blockIdx.x;
    __shared__ float ur[NF], ui[NF];
    __shared__ float twr[96], twi[96];
    int t = threadIdx.x;
    const float* Ur = g_Xre + (size_t)bc*NF;
    const float* Ui = g_Xim + (size_t)bc*NF;
    for (int i=t;i<NF;i+=256){ ur[i]=Ur[i]; ui[i]=Ui[i]; }
    if (t<96){ float s,c; sincospif((float)t*(1.f/48.f), &s,&c); twr[t]=c; twi[t]=s; }
    __syncthreads();
    float bbv = g_bb[bc];
    for (int tile=t; tile<576; tile+=256){
        int y0 = (tile/48)*8;
        int x1 = (tile%48)*2, x2 = x1+1;
        float aA[8], aB[8];
        #pragma unroll
        for (int i=0;i<8;i++){ aA[i]=0.f; aB[i]=0.f; }
        int k1=x1, k2=x2;
        for (int fx=1; fx<48; fx++){
            float c1=twr[k1], s1=twi[k1], c2=twr[k2], s2=twi[k2];
            #pragma unroll
            for (int i=0;i<8;i++){
                float vr=ur[(y0+i)*49+fx], vi=ui[(y0+i)*49+fx];
                aA[i] += vr*c1 - vi*s1;
                aB[i] += vr*c2 - vi*s2;
            }
            k1 += x1; if (k1>=96) k1-=96;
            k2 += x2; if (k2>=96) k2-=96;
        }
        #pragma unroll
        for (int i=0;i<8;i++){
            float u0  = ur[(y0+i)*49];
            float u48 = ur[(y0+i)*49+48];
            float vA = (u0 + u48 + 2.f*aA[i])*(1.f/9216.f);
            float vB = (u0 - u48 + 2.f*aB[i])*(1.f/9216.f);
            size_t idx = (size_t)bc*NN + (y0+i)*96 + x1;
            g_xfft[idx]   = g_ximg[idx]   + FFT_RES_C*(vA + bbv);
            g_xfft[idx+1] = g_ximg[idx+1] + FFT_RES_C*(vB + bbv);
        }
    }
}

/* ---------- CAB conv1 180->60 3x3 + GELU : 4px x 16oc tiles, float4 weights ---------- */
__global__ void k_conv1(const float* __restrict__ bias){
    int bi = blockIdx.x; int b = bi/36; int tile = bi%36;
    int ty0 = (tile/6)*16, tx0 = (tile%6)*16;
    __shared__ float ins[12*324];
    __shared__ __align__(16) float ws[12*9*64];
    int t = threadIdx.x;
    int oid = t>>6;
    int pxid = t&63;
    int px0 = (pxid&7)*2, py0 = (pxid>>3)*2;
    float acc[16][4];
    #pragma unroll
    for (int j=0;j<16;j++){ acc[j][0]=0.f;acc[j][1]=0.f;acc[j][2]=0.f;acc[j][3]=0.f; }
    for (int ic0=0; ic0<180; ic0+=12){
        __syncthreads();
        for (int i=t;i<12*324;i+=256){
            int icl=i/324, r=i%324; int hy=r/18, hx=r%18;
            int gy=ty0+hy-1, gx=tx0+hx-1;
            float v=0.f;
            if (gy>=0 && gy<96 && gx>=0 && gx<96)
                v = g_xfft[((size_t)(b*CC+ic0+icl))*NN + gy*96+gx];
            ins[i]=v;
        }
        for (int i=t;i<6912;i+=256){
            int q=i>>6, o=i&63;
            ws[i] = (o<60) ? g_w1t[ic0*540 + q*60 + o] : 0.f;
        }
        __syncthreads();
        for (int icl=0; icl<12; icl++){
            #pragma unroll
            for (int tap=0;tap<9;tap++){
                int dy=tap/3, dx=tap%3;
                int base = icl*324 + (py0+dy)*18 + (px0+dx);
                float v0=ins[base], v1=ins[base+1], v2=ins[base+18], v3=ins[base+19];
                const float4* wp4 = (const float4*)&ws[(icl*9+tap)*64 + oid*16];
                float4 wa=wp4[0], wb=wp4[1], wcc=wp4[2], wd=wp4[3];
                float wv[16]={wa.x,wa.y,wa.z,wa.w, wb.x,wb.y,wb.z,wb.w,
                              wcc.x,wcc.y,wcc.z,wcc.w, wd.x,wd.y,wd.z,wd.w};
                #pragma unroll
                for (int j=0;j<16;j++){
                    float w = wv[j];
                    acc[j][0]+=w*v0; acc[j][1]+=w*v1;
                    acc[j][2]+=w*v2; acc[j][3]+=w*v3;
                }
            }
        }
    }
    #pragma unroll
    for (int j=0;j<16;j++){
        int o = oid*16+j;
        if (o < 60){
            float bv = bias[o];
            #pragma unroll
            for (int p=0;p<4;p++){
                int n = (ty0+py0+(p>>1))*96 + tx0+px0+(p&1);
                g_mid[((size_t)(b*60+o))*NN + n] = gelu_exact(acc[j][p]+bv);
            }
        }
    }
}

/* ---------- CAB conv2 60->180 3x3 : 4px x 16oc tiles, float4 weights ---------- */
__global__ void k_conv2(const float* __restrict__ bias){
    int bx = blockIdx.x;
    int b = bx/108; int r = bx%108; int tile = r/3; int oc0 = (r%3)*60;
    int ty0 = (tile/6)*16, tx0 = (tile%6)*16;
    __shared__ float ins[12*324];
    __shared__ __align__(16) float ws[12*9*64];
    int t = threadIdx.x;
    int oid = t>>6;
    int pxid = t&63;
    int px0 = (pxid&7)*2, py0 = (pxid>>3)*2;
    float acc[16][4];
    #pragma unroll
    for (int j=0;j<16;j++){ acc[j][0]=0.f;acc[j][1]=0.f;acc[j][2]=0.f;acc[j][3]=0.f; }
    for (int ic0=0; ic0<60; ic0+=12){
        __syncthreads();
        for (int i=t;i<12*324;i+=256){
            int icl=i/324, rr=i%324; int hy=rr/18, hx=rr%18;
            int gy=ty0+hy-1, gx=tx0+hx-1;
            float v=0.f;
            if (gy>=0 && gy<96 && gx>=0 && gx<96)
                v = g_mid[((size_t)(b*60+ic0+icl))*NN + gy*96+gx];
            ins[i]=v;
        }
        for (int i=t;i<6912;i+=256){
            int q=i>>6, o=i&63;
            ws[i] = (o<60) ? g_w2t[(ic0*9+q)*CC + oc0 + o] : 0.f;
        }
        __syncthreads();
        for (int icl=0; icl<12; icl++){
            #pragma unroll
            for (int tap=0;tap<9;tap++){
                int dy=tap/3, dx=tap%3;
                int base = icl*324 + (py0+dy)*18 + (px0+dx);
                float v0=ins[base], v1=ins[base+1], v2=ins[base+18], v3=ins[base+19];
                const float4* wp4 = (const float4*)&ws[(icl*9+tap)*64 + oid*16];
                float4 wa=wp4[0], wb=wp4[1], wcc=wp4[2], wd=wp4[3];
                float wv[16]={wa.x,wa.y,wa.z,wa.w, wb.x,wb.y,wb.z,wb.w,
                              wcc.x,wcc.y,wcc.z,wcc.w, wd.x,wd.y,wd.z,wd.w};
                #pragma unroll
                for (int j=0;j<16;j++){
                    float w = wv[j];
                    acc[j][0]+=w*v0; acc[j][1]+=w*v1;
                    acc[j][2]+=w*v2; acc[j][3]+=w*v3;
                }
            }
        }
    }
    #pragma unroll
    for (int j=0;j<16;j++){
        int ol = oid*16+j;
        if (ol < 60){
            int o = oc0 + ol;
            float bv = bias[o];
            #pragma unroll
            for (int p=0;p<4;p++){
                int n = (ty0+py0+(p>>1))*96 + tx0+px0+(p&1);
                g_y2[((size_t)(b*CC+o))*NN + n] = acc[j][p]+bv;
            }
        }
    }
}

__global__ void k_eca(const float* __restrict__ ew){
    int b = blockIdx.x; int c = threadIdx.x;
    if (c < CC){
        float z = 0.f;
        for (int i=0;i<5;i++){
            int idx=c-2+i;
            if (idx>=0 && idx<CC) z += g_gap[b*CC+idx]*ew[i];
        }
        g_eca[b*CC+c] = sigm(z);
    }
}

__global__ void k_dwc(const float* __restrict__ w1, const float* __restrict__ b1,
                      const float* __restrict__ w2, const float* __restrict__ b2){
    int b = blockIdx.x; int t = threadIdx.x;
    __shared__ float hdn[8];
    if (t < 8){
        float a = b1[t];
        for (int p=0;p<16;p++) a += g_cmean[b*CC+p]*w1[t*16+p];
        hdn[t] = gelu_exact(a);
    }
    __syncthreads();
    if (t < 144){
        float a = b2[t];
        for (int o=0;o<8;o++) a += hdn[o]*w2[t*8+o];
        g_dk[b*144+t] = a;
    }
}

/* ---------- 13x13 LK + dynamic 3x3 : 2x2px x 4oc tiles, smem weights ---------- */
__global__ void k_lkdyn(const float* __restrict__ plk){
    int bi = blockIdx.x; int b = bi/36; int tile = bi%36;
    int ty0 = (tile/6)*16, tx0 = (tile%6)*16;
    __shared__ float ins[28*28];
    __shared__ float wlk[16*169];
    __shared__ float dks[144];
    int t = threadIdx.x;
    int ocg = t>>6; int pxid = t&63;
    int px0=(pxid&7)*2, py0=(pxid>>3)*2;
    if (t < 144) dks[t]=g_dk[b*144+t];
    float acc[4][4];
    #pragma unroll
    for (int j=0;j<4;j++){ acc[j][0]=0.f;acc[j][1]=0.f;acc[j][2]=0.f;acc[j][3]=0.f; }
    for (int ic=0; ic<16; ic++){
        __syncthreads();
        for (int i=t;i<784;i+=256){
            int hy=i/28, hx=i%28;
            int gy=ty0+hy-6, gx=tx0+hx-6;
            float v=0.f;
            if (gy>=0 && gy<96 && gx>=0 && gx<96)
                v = g_ximg[((size_t)(b*CC+ic))*NN + gy*96+gx];
            ins[i]=v;
        }
        for (int i=t;i<2704;i+=256){
            int oc=i/169, tap=i%169;
            wlk[i] = plk[(oc*16+ic)*169 + tap];
        }
        __syncthreads();
        for (int ky=0;ky<13;ky++){
            #pragma unroll
            for (int kx=0;kx<13;kx++){
                int base = (py0+ky)*28 + px0+kx;
                float v0=ins[base], v1=ins[base+1], v2=ins[base+28], v3=ins[base+29];
                #pragma unroll
                for (int j=0;j<4;j++){
                    float wv = wlk[(ocg*4+j)*169 + ky*13+kx];
                    acc[j][0]+=wv*v0; acc[j][1]+=wv*v1;
                    acc[j][2]+=wv*v2; acc[j][3]+=wv*v3;
                }
            }
        }
        if ((ic>>2)==ocg){
            int j = ic&3;
            #pragma unroll
            for (int tap=0;tap<9;tap++){
                int dy=tap/3, dx=tap%3;
                int base=(py0+5+dy)*28 + px0+5+dx;
                float wv = dks[ic*9+tap];
                acc[j][0]+=wv*ins[base];   acc[j][1]+=wv*ins[base+1];
                acc[j][2]+=wv*ins[base+28];acc[j][3]+=wv*ins[base+29];
            }
        }
    }
    #pragma unroll
    for (int j=0;j<4;j++){
        int oc = ocg*4+j;
        #pragma unroll
        for (int p=0;p<4;p++){
            int n = (ty0+py0+(p>>1))*96 + tx0+px0+(p&1);
            g_att16[((size_t)(b*16+oc))*NN + n] = acc[j][p];
        }
    }
}

/* ---------- aggr 1x1 + residual assembly, 32-px tiles ---------- */
__global__ void k_xm(const float* __restrict__ x, const float* __restrict__ ab){
    int bi = blockIdx.x; int b = bi/288; int n0 = (bi%288)*32;
    __shared__ __align__(16) float us[180*32];
    int t = threadIdx.x;
    for (int i=t;i<180*32;i+=192){
        int c=i>>5, p=i&31;
        float v = (c<16) ? g_att16[((size_t)(b*16+c))*NN + n0+p]
                         : g_ximg [((size_t)(b*CC+c))*NN + n0+p];
        us[i]=v;
    }
    __syncthreads();
    float acc[32];
    if (t < 180){
        float bv = ab[t];
        #pragma unroll
        for (int p=0;p<32;p++) acc[p]=bv;
        for (int c=0;c<180;c++){
            float w = g_aggrT[c*180+t];
            #pragma unroll
            for (int p=0;p<32;p++) acc[p] += w*us[c*32+p];
        }
        float e = g_eca[b*180+t];
        const float* yp = &g_y2[((size_t)(b*180+t))*NN + n0];
        #pragma unroll
        for (int p=0;p<32;p++) acc[p] += CONV_SCALE_C*e*yp[p];
    }
    __syncthreads();
    if (t < 180){
        #pragma unroll
        for (int p=0;p<32;p++) us[p*180+t]=acc[p];
    }
    __syncthreads();
    for (int i=t;i<32*180;i+=192){
        size_t idx = ((size_t)(b*NN)+n0+(i/180))*CC + (i%180);
        g_xm[idx] = x[idx] + us[i];
    }
}

/* ---------- LN2 + fc1, 4d x 8px register tiles + float4 ---------- */
__global__ void k_ln2fc1(const float* __restrict__ g2, const float* __restrict__ b2,
                         const float* __restrict__ fb){
    int bi = blockIdx.x; int b = bi/288; int n0 = (bi%288)*32;
    __shared__ __align__(16) float xs[180*36];
    __shared__ float mean_[32], rinv_[32];
    int t = threadIdx.x;
    for (int i=t;i<32*180;i+=256){
        int p=i/180, c=i%180;
        xs[c*36+p] = g_xm[((size_t)(b*NN)+n0+p)*CC + c];
    }
    __syncthreads();
    int wid=t>>5, lane=t&31;
    for (int r=wid;r<32;r+=8){
        float s=0.f, q=0.f;
        for (int c=lane;c<180;c+=32){ float v=xs[c*36+r]; s+=v; q+=v*v; }
        for (int off=16;off;off>>=1){
            s += __shfl_xor_sync(0xffffffffu,s,off);
            q += __shfl_xor_sync(0xffffffffu,q,off);
        }
        if (lane==0){
            float m = s/180.f;
            mean_[r]=m;
            rinv_[r]=rsqrtf(q/180.f - m*m + EPS_C);
        }
    }
    __syncthreads();
    for (int i=t;i<180*32;i+=256){
        int c=i/32, r=i&31;
        xs[c*36+r] = (xs[c*36+r]-mean_[r])*rinv_[r]*g2[c] + b2[c];
    }
    __syncthreads();
    if (t < 240){
        int dq=t>>2, pq=t&3;
        for (int pass=0;pass<3;pass++){
            int d0 = pass*240 + dq*4;
            float acc[4][8];
            #pragma unroll
            for (int j=0;j<4;j++){
                float bv = fb[d0+j];
                #pragma unroll
                for (int p=0;p<8;p++) acc[j][p]=bv;
            }
            for (int c=0;c<180;c++){
                float4 w  = *(const float4*)&g_fc1T[c*720 + d0];
                float4 xa = *(const float4*)&xs[c*36 + pq*8];
                float4 xb = *(const float4*)&xs[c*36 + pq*8 + 4];
                float xv[8] = {xa.x,xa.y,xa.z,xa.w, xb.x,xb.y,xb.z,xb.w};
                #pragma unroll
                for (int p=0;p<8;p++){
                    acc[0][p] += w.x*xv[p];
                    acc[1][p] += w.y*xv[p];
                    acc[2][p] += w.z*xv[p];
                    acc[3][p] += w.w*xv[p];
                }
            }
            #pragma unroll
            for (int j=0;j<4;j++){
                float* op = &g_t[((size_t)(b*720+d0+j))*NN + n0 + pq*8];
                *(float4*)op     = make_float4(acc[j][0],acc[j][1],acc[j][2],acc[j][3]);
                *(float4*)(op+4) = make_float4(acc[j][4],acc[j][5],acc[j][6],acc[j][7]);
            }
        }
    }
}

/* ---------- depthwise 3x3 + GLU : 32x32 smem tiles, 4px/thread ---------- */
__global__ void k_dwglu(const float* __restrict__ dww, const float* __restrict__ dwb){
    int bx = blockIdx.x;
    int tile = bx%9; int bh = bx/9; int b = bh/HIDV; int h = bh%HIDV;
    int ty0 = (tile/3)*32, tx0 = (tile%3)*32;
    __shared__ float sp[34*34], sg[34*34];
    int t = threadIdx.x;
    const float* tp = g_t + ((size_t)(b*H2V+h))*NN;
    const float* tg = tp + (size_t)HIDV*NN;
    for (int i=t;i<1156;i+=256){
        int hy=i/34, hx=i%34;
        int gy=ty0+hy-1, gx=tx0+hx-1;
        bool ok = (gy>=0 && gy<96 && gx>=0 && gx<96);
        int src = gy*96+gx;
        sp[i] = ok ? tp[src] : 0.f;
        sg[i] = ok ? tg[src] : 0.f;
    }
    float wp[9], wg[9];
    #pragma unroll
    for (int j=0;j<9;j++){ wp[j]=dww[h*9+j]; wg[j]=dww[(h+HIDV)*9+j]; }
    float bp = dwb[h], bg = dwb[h+HIDV];
    __syncthreads();
    int lx = t&31, ly0 = (t>>5)*4;
    float* op = g_act + ((size_t)(b*HIDV+h))*NN;
    #pragma unroll
    for (int q=0;q<4;q++){
        int ly = ly0+q;
        float pa=bp, ga=bg;
        #pragma unroll
        for (int dy=0;dy<3;dy++){
            int base = (ly+dy)*34 + lx;
            pa += wp[dy*3+0]*sp[base]   + wp[dy*3+1]*sp[base+1]   + wp[dy*3+2]*sp[base+2];
            ga += wg[dy*3+0]*sg[base]   + wg[dy*3+1]*sg[base+1]   + wg[dy*3+2]*sg[base+2];
        }
        op[(ty0+ly)*96 + tx0+lx] = pa * (ga*sigm(ga));
    }
}

/* ---------- fc2 + final residual, 4d x 8px tiles + float4 ---------- */
__global__ void k_fc2(const float* __restrict__ fb, float* __restrict__ out){
    int bi = blockIdx.x; int b = bi/288; int n0 = (bi%288)*32;
    __shared__ __align__(16) float sh[360*32];
    int t = threadIdx.x;
    for (int i=t;i<360*32;i+=192){
        int h=i>>5, p=i&31;
        sh[i] = g_act[((size_t)(b*360+h))*NN + n0 + p];
    }
    __syncthreads();
    int dq=t>>2, pq=t&3;
    if (dq < 45){
        int d0 = dq*4;
        float acc[8][4];
        #pragma unroll
        for (int p=0;p<8;p++){
            acc[p][0]=fb[d0]; acc[p][1]=fb[d0+1];
            acc[p][2]=fb[d0+2]; acc[p][3]=fb[d0+3];
        }
        for (int h=0;h<360;h++){
            float4 w  = *(const float4*)&g_fc2T[h*180 + d0];
            float4 xa = *(const float4*)&sh[h*32 + pq*8];
            float4 xb = *(const float4*)&sh[h*32 + pq*8 + 4];
            float xv[8] = {xa.x,xa.y,xa.z,xa.w, xb.x,xb.y,xb.z,xb.w};
            #pragma unroll
            for (int p=0;p<8;p++){
                acc[p][0] += w.x*xv[p];
                acc[p][1] += w.y*xv[p];
                acc[p][2] += w.z*xv[p];
                acc[p][3] += w.w*xv[p];
            }
        }
        #pragma unroll
        for (int p=0;p<8;p++){
            size_t base = ((size_t)(b*NN)+n0+pq*8+p)*CC + d0;
            float4 xm4 = *(const float4*)&g_xm[base];
            float4 o4;
            o4.x = xm4.x + acc[p][0];
            o4.y = xm4.y + acc[p][1];
            o4.z = xm4.z + acc[p][2];
            o4.w = xm4.w + acc[p][3];
            *(float4*)&out[base] = o4;
        }
    }
}

extern "C" void kernel_launch(void* const* d_in, const int* in_sizes, int n_in,
                              void* d_out, int out_size){
    (void)in_sizes; (void)n_in; (void)out_size;
    const float* x      = (const float*)d_in[0];
    const float* ln1_g  = (const float*)d_in[3];
    const float* ln1_b  = (const float*)d_in[4];
    const float* band_w = (const float*)d_in[5];
    const float* band_b = (const float*)d_in[6];
    const float* gate_w = (const float*)d_in[7];
    const float* gate_b = (const float*)d_in[8];
    const float* cab_w1 = (const float*)d_in[9];
    const float* cab_b1 = (const float*)d_in[10];
    const float* cab_w2 = (const float*)d_in[11];
    const float* cab_b2 = (const float*)d_in[12];
    const float* eca_w  = (const float*)d_in[13];
    const float* plk    = (const float*)d_in[14];
    const float* dwc_w1 = (const float*)d_in[15];
    const float* dwc_b1 = (const float*)d_in[16];
    const float* dwc_w2 = (const float*)d_in[17];
    const float* dwc_b2 = (const float*)d_in[18];
    const float* aggr_w = (const float*)d_in[19];
    const float* aggr_b = (const float*)d_in[20];
    const float* ln2_g  = (const float*)d_in[21];
    const float* ln2_b  = (const float*)d_in[22];
    const float* fc1_w  = (const float*)d_in[23];
    const float* fc1_b  = (const float*)d_in[24];
    const float* dw_w   = (const float*)d_in[25];
    const float* dw_b   = (const float*)d_in[26];
    const float* fc2_w  = (const float*)d_in[27];
    const float* fc2_b  = (const float*)d_in[28];
    float* out = (float*)d_out;

    k_transpose<<<512,256>>>(band_w, aggr_w, fc1_w, fc2_w, cab_w1, cab_w2);
    k_ln1<<<BB*NN/32,256>>>(x, ln1_g, ln1_b);
    k_chanmean<<<BB*CC,256>>>(0);
    k_gates<<<BB,192>>>(gate_w, gate_b, band_b);
    k_rowdft<<<BB*CC,256>>>();
    k_cdft<<<BB*CC,256>>>(0);
    k_freqmm<<<BB*96,192>>>();
    k_cdft<<<BB*CC,256>>>(1);
    k_irow<<<BB*CC,256>>>();
    k_conv1<<<BB*36,256>>>(cab_b1);
    k_conv2<<<BB*108,256>>>(cab_b2);
    k_chanmean<<<BB*CC,256>>>(1);
    k_eca<<<BB,192>>>(eca_w);
    k_dwc<<<BB,192>>>(dwc_w1, dwc_b1, dwc_w2, dwc_b2);
    k_lkdyn<<<BB*36,256>>>(plk);
    k_xm<<<BB*288,192>>>(x, aggr_b);
    k_ln2fc1<<<BB*288,256>>>(ln2_g, ln2_b, fc1_b);
    k_dwglu<<<BB*HIDV*9,256>>>(dw_w, dw_b);
    k_fc2<<<BB*288,192>>>(fc2_b, out);
}